// round 4
// baseline (speedup 1.0000x reference)
#include <cuda_runtime.h>
#include <cuda_fp16.h>
#include <math.h>

#define Bn   256
#define Hn   1024
#define XDn  192
#define YDn  64
#define INn  256
#define PREn 64
#define FWDn 48
#define G4H  4096

// ---------------- scratch (device globals; no allocations allowed) ----------
// gate-interleaved packed weights: packed row = 4*unit + gate
__device__ __half g_W0h[G4H * 1280], g_W0l[G4H * 1280];
__device__ __half g_W1h[G4H * 2048], g_W1l[G4H * 2048];
__device__ __half g_Wfh[Hn * Hn],    g_Wfl[Hn * Hn];
__device__ float  g_bp0[G4H], g_bp1[G4H];           // packed b_ih+b_hh
// encode inputs [x_t|y_t] hi/lo: (64, 256, 256)
__device__ __half g_XYh[PREn * Bn * INn], g_XYl[PREn * Bn * INn];
// decode inputs [fx_t|est_t] hi/lo: (48, 256, 256)
__device__ __half g_FXh[FWDn * Bn * INn], g_FXl[FWDn * Bn * INn];
// ping-pong hidden states (hi/lo halves)
__device__ __half g_H0h[2][Bn * Hn], g_H0l[2][Bn * Hn];
__device__ __half g_H1h[2][Bn * Hn], g_H1l[2][Bn * Hn];
// fp32 state
__device__ float g_c0[Bn * Hn], g_c1[Bn * Hn];
__device__ float g_t1[Bn * Hn], g_est[Bn * YDn];

// ---------------- helpers ----------------------------------------------------
__device__ __forceinline__ float sigf(float x) { return 1.0f / (1.0f + expf(-x)); }

__device__ __forceinline__ void cpa16(void* dst, const void* src) {
    unsigned d = (unsigned)__cvta_generic_to_shared(dst);
    asm volatile("cp.async.cg.shared.global [%0], [%1], 16;\n" :: "r"(d), "l"(src));
}

__device__ __forceinline__ void ldsm_x4(unsigned r[4], const unsigned* p) {
    unsigned addr = (unsigned)__cvta_generic_to_shared(p);
    asm volatile("ldmatrix.sync.aligned.m8n8.x4.shared.b16 {%0,%1,%2,%3}, [%4];\n"
        : "=r"(r[0]), "=r"(r[1]), "=r"(r[2]), "=r"(r[3]) : "r"(addr));
}

__device__ __forceinline__ void mma16816(float c[4], const unsigned a[4], const unsigned b[2]) {
    asm volatile(
        "mma.sync.aligned.m16n8k16.row.col.f32.f16.f16.f32 "
        "{%0,%1,%2,%3}, {%4,%5,%6,%7}, {%8,%9}, {%0,%1,%2,%3};\n"
        : "+f"(c[0]), "+f"(c[1]), "+f"(c[2]), "+f"(c[3])
        : "r"(a[0]), "r"(a[1]), "r"(a[2]), "r"(a[3]), "r"(b[0]), "r"(b[1]));
}

// ---------------- fp16x3 GEMM + fused epilogue ------------------------------
#define BM 64
#define BN 128
#define BK 32            // halves per k tile
#define RS 20            // smem row stride in 4B units (16 data + 4 pad)
#define OFF_AH 0
#define OFF_AL (BM * RS)
#define OFF_WH (2 * BM * RS)
#define OFF_WL (2 * BM * RS + BN * RS)
#define STAGE  (2 * BM * RS + 2 * BN * RS)   // 7680 uints = 30720 B
#define NSTG   3
#define SMEMB  (NSTG * STAGE * 4)            // 92160 B

__device__ __forceinline__ void load_tile(
    unsigned* sm, int sbase, int k0, int m0, int n0, int tid,
    const __half* a0h, const __half* a0l, int w0, int lda0,
    const __half* a1h, const __half* a1l, int lda1,
    const __half* wgh, const __half* wgl, int ldw)
{
    const __half *ah, *al; int lda, koff;
    if (k0 < w0) { ah = a0h; al = a0l; lda = lda0; koff = k0; }
    else         { ah = a1h; al = a1l; lda = lda1; koff = k0 - w0; }
#pragma unroll
    for (int i = 0; i < 2; i++) {           // A: 512 16B chunks (hi+lo)
        int c = tid + (i << 8);
        int part = c >> 8;
        int row  = (c & 255) >> 2;
        int kc   = c & 3;
        const __half* src = (part ? al : ah) + (size_t)(m0 + row) * lda + koff + kc * 8;
        unsigned* dst = sm + sbase + (part ? OFF_AL : OFF_AH) + row * RS + kc * 4;
        cpa16(dst, src);
    }
#pragma unroll
    for (int i = 0; i < 4; i++) {           // W: 1024 16B chunks (hi+lo)
        int c = tid + (i << 8);
        int part = c >> 9;
        int row  = (c & 511) >> 2;
        int kc   = c & 3;
        const __half* src = (part ? wgl : wgh) + (size_t)(n0 + row) * ldw + k0 + kc * 8;
        unsigned* dst = sm + sbase + (part ? OFF_WL : OFF_WH) + row * RS + kc * 4;
        cpa16(dst, src);
    }
}

// mode 0: LSTM-cell epilogue (gate-interleaved W): updates cst in place,
//         writes h hi/lo.  mode 1: out = tanh(acc + bias).
__global__ void __launch_bounds__(256) gemm_fp16x3(
    const __half* __restrict__ a0h, const __half* __restrict__ a0l, int w0, int lda0,
    const __half* __restrict__ a1h, const __half* __restrict__ a1l, int lda1,
    const __half* __restrict__ wgh, const __half* __restrict__ wgl, int ldw,
    int K, int N,
    const float* __restrict__ bias, int mode,
    float* __restrict__ out,
    float* __restrict__ cst, __half* __restrict__ Hh, __half* __restrict__ Hl)
{
    extern __shared__ unsigned sm[];
    const int tid  = threadIdx.x;
    const int warp = tid >> 5;
    const int lane = tid & 31;
    const int m0 = blockIdx.y * BM;
    const int n0 = blockIdx.x * BN;
    const int wm = (warp & 1) * 32;    // warps 2(M) x 4(N); warp tile 32x32
    const int wn = (warp >> 1) * 32;
    const int gr = lane >> 2;
    const int tg = lane & 3;
    // ldmatrix per-lane address components
    const int a_row  = wm + (lane & 15);
    const int a_colu = (lane >> 4) << 2;
    const int b_row  = wn + (lane & 7) + ((lane >> 4) << 3);
    const int b_colu = ((lane >> 3) & 1) << 2;

    float acc[2][4][4];
#pragma unroll
    for (int mi = 0; mi < 2; mi++)
#pragma unroll
        for (int ni = 0; ni < 4; ni++)
#pragma unroll
            for (int e = 0; e < 4; e++) acc[mi][ni][e] = 0.0f;

    const int NT = K / BK;
    load_tile(sm, 0, 0, m0, n0, tid, a0h, a0l, w0, lda0, a1h, a1l, lda1, wgh, wgl, ldw);
    asm volatile("cp.async.commit_group;\n");
    if (NT > 1) {
        load_tile(sm, STAGE, BK, m0, n0, tid, a0h, a0l, w0, lda0, a1h, a1l, lda1, wgh, wgl, ldw);
        asm volatile("cp.async.commit_group;\n");
    }

    for (int kt = 0; kt < NT; kt++) {
        if (kt + 2 < NT) {
            load_tile(sm, ((kt + 2) % NSTG) * STAGE, (kt + 2) * BK, m0, n0, tid,
                      a0h, a0l, w0, lda0, a1h, a1l, lda1, wgh, wgl, ldw);
            asm volatile("cp.async.commit_group;\n");
            asm volatile("cp.async.wait_group 2;\n");
        } else if (kt + 1 < NT) {
            asm volatile("cp.async.wait_group 1;\n");
        } else {
            asm volatile("cp.async.wait_group 0;\n");
        }
        __syncthreads();

        const unsigned* sb = sm + (kt % NSTG) * STAGE;
#pragma unroll
        for (int ks = 0; ks < 2; ks++) {
            const int co = ks * 8;
            unsigned ah[2][4], al[2][4], bh[4][2], bl[4][2];
#pragma unroll
            for (int mi = 0; mi < 2; mi++) {
                ldsm_x4(ah[mi], sb + OFF_AH + (a_row + mi * 16) * RS + co + a_colu);
                ldsm_x4(al[mi], sb + OFF_AL + (a_row + mi * 16) * RS + co + a_colu);
            }
#pragma unroll
            for (int np = 0; np < 2; np++) {
                unsigned th[4], tl[4];
                ldsm_x4(th, sb + OFF_WH + (b_row + np * 16) * RS + co + b_colu);
                ldsm_x4(tl, sb + OFF_WL + (b_row + np * 16) * RS + co + b_colu);
                bh[2*np][0] = th[0]; bh[2*np][1] = th[1];
                bh[2*np+1][0] = th[2]; bh[2*np+1][1] = th[3];
                bl[2*np][0] = tl[0]; bl[2*np][1] = tl[1];
                bl[2*np+1][0] = tl[2]; bl[2*np+1][1] = tl[3];
            }
#pragma unroll
            for (int mi = 0; mi < 2; mi++)
#pragma unroll
                for (int ni = 0; ni < 4; ni++) {
                    mma16816(acc[mi][ni], al[mi], bh[ni]);
                    mma16816(acc[mi][ni], ah[mi], bl[ni]);
                    mma16816(acc[mi][ni], ah[mi], bh[ni]);
                }
        }
        __syncthreads();
    }

    if (mode == 1) {
#pragma unroll
        for (int mi = 0; mi < 2; mi++)
#pragma unroll
            for (int ni = 0; ni < 4; ni++) {
                int row0 = m0 + wm + mi * 16 + gr;
                int col0 = n0 + wn + ni * 8 + tg * 2;
#pragma unroll
                for (int e = 0; e < 4; e++) {
                    int r = row0 + (e >> 1) * 8;
                    int c = col0 + (e & 1);
                    out[r * N + c] = tanhf(acc[mi][ni][e] + bias[c]);
                }
            }
    } else {
        // gate-interleaved cell epilogue: cols 4u+{0,1,2,3} = i,f,g,o
#pragma unroll
        for (int mi = 0; mi < 2; mi++)
#pragma unroll
            for (int ni = 0; ni < 4; ni++) {
                int r0 = m0 + wm + mi * 16 + gr;
                int cb = n0 + wn + ni * 8 + tg * 2;
                float v0 = acc[mi][ni][0] + bias[cb];
                float v1 = acc[mi][ni][1] + bias[cb + 1];
                float v2 = acc[mi][ni][2] + bias[cb];
                float v3 = acc[mi][ni][3] + bias[cb + 1];
                float p0 = __shfl_xor_sync(0xffffffffu, v0, 1);
                float p1 = __shfl_xor_sync(0xffffffffu, v1, 1);
                float p2 = __shfl_xor_sync(0xffffffffu, v2, 1);
                float p3 = __shfl_xor_sync(0xffffffffu, v3, 1);
                if (!(tg & 1)) {
                    // this lane: (i,f); partner lane: (g,o)
                    int u = cb >> 2;
                    int i0 = r0 * Hn + u;
                    float cn = sigf(v1) * cst[i0] + sigf(v0) * tanhf(p0);
                    cst[i0] = cn;
                    float hn = sigf(p1) * tanhf(cn);
                    __half hv = __float2half_rn(hn);
                    Hh[i0] = hv; Hl[i0] = __float2half_rn(hn - __half2float(hv));
                    int i1 = i0 + 8 * Hn;
                    float cn2 = sigf(v3) * cst[i1] + sigf(v2) * tanhf(p2);
                    cst[i1] = cn2;
                    float hn2 = sigf(p3) * tanhf(cn2);
                    __half hv2 = __float2half_rn(hn2);
                    Hh[i1] = hv2; Hl[i1] = __float2half_rn(hn2 - __half2float(hv2));
                }
            }
    }
}

// ---------------- hi/lo split; optional gate-interleave row remap ------------
__global__ void __launch_bounds__(256) split_kernel(
    const float* __restrict__ src, __half* __restrict__ dh, __half* __restrict__ dl,
    int w, int ldd, int off, int total, int remap)
{
    for (int idx = blockIdx.x * 256 + threadIdx.x; idx < total; idx += gridDim.x * 256) {
        int n = idx / w;
        int k = idx - n * w;
        int pr = remap ? (((n & 1023) << 2) | (n >> 10)) : n;
        float v = src[idx];
        __half h = __float2half_rn(v);
        int d = pr * ldd + off + k;
        dh[d] = h;
        dl[d] = __float2half_rn(v - __half2float(h));
    }
}

__global__ void __launch_bounds__(256) biaspack_kernel(
    const float* __restrict__ bi, const float* __restrict__ bh, float* __restrict__ op)
{
    int n = blockIdx.x * 256 + threadIdx.x;
    if (n < G4H) {
        int u = n & 1023, g = n >> 10;
        op[4 * u + g] = bi[n] + bh[n];
    }
}

// ---------------- fc2 + residual est; writes output + est halves into FX ----
__global__ void __launch_bounds__(256) fc2_est_kernel(
    const float* __restrict__ t1, const float* __restrict__ w2,
    const float* __restrict__ b2, float* __restrict__ est,
    float* __restrict__ outp, __half* __restrict__ fh, __half* __restrict__ fl)
{
    int gw = (blockIdx.x * 256 + threadIdx.x) >> 5;
    int lane = threadIdx.x & 31;
    int b = gw >> 6;
    int j = gw & 63;
    const float* trow = t1 + b * Hn;
    const float* wrow = w2 + j * Hn;
    float s = 0.0f;
#pragma unroll 8
    for (int k = lane; k < Hn; k += 32) s += trow[k] * wrow[k];
#pragma unroll
    for (int o = 16; o; o >>= 1) s += __shfl_xor_sync(0xffffffffu, s, o);
    if (lane == 0) {
        float v = s + b2[j] + est[b * YDn + j];
        est[b * YDn + j] = v;
        outp[b * YDn + j] = v;
        __half hh = __float2half_rn(v);
        int d = b * INn + XDn + j;
        fh[d] = hh;
        fl[d] = __float2half_rn(v - __half2float(hh));
    }
}

// ---------------- init ----------------
__global__ void __launch_bounds__(256) init_kernel(const float* __restrict__ pre_y)
{
    int i = blockIdx.x * 256 + threadIdx.x;
    if (i < Bn * Hn) {
        g_c0[i] = 0.0f; g_c1[i] = 0.0f;
        __half z = __float2half_rn(0.0f);
        g_H0h[0][i] = z; g_H0l[0][i] = z;
        g_H1h[0][i] = z; g_H1l[0][i] = z;
    }
    if (i < Bn * YDn) g_est[i] = pre_y[(PREn - 1) * Bn * YDn + i];
}

// ---------------- launch -----------------------------------------------------
extern "C" void kernel_launch(void* const* d_in, const int* in_sizes, int n_in,
                              void* d_out, int out_size)
{
    const float* pre_x  = (const float*)d_in[0];
    const float* pre_y  = (const float*)d_in[1];
    const float* fwd_x  = (const float*)d_in[2];
    const float* w_ih0  = (const float*)d_in[3];
    const float* w_hh0  = (const float*)d_in[4];
    const float* b_ih0  = (const float*)d_in[5];
    const float* b_hh0  = (const float*)d_in[6];
    const float* w_ih1  = (const float*)d_in[7];
    const float* w_hh1  = (const float*)d_in[8];
    const float* b_ih1  = (const float*)d_in[9];
    const float* b_hh1  = (const float*)d_in[10];
    const float* fc_w1  = (const float*)d_in[11];
    const float* fc_b1  = (const float*)d_in[12];
    const float* fc_w2  = (const float*)d_in[13];
    const float* fc_b2  = (const float*)d_in[14];
    float* outp = (float*)d_out;

    cudaFuncSetAttribute(gemm_fp16x3, cudaFuncAttributeMaxDynamicSharedMemorySize, SMEMB);

    void *pv;
    #define SYM(name, var) cudaGetSymbolAddress(&pv, var); auto* name = (decltype(&var[0]))pv;
    SYM(W0h, g_W0h) SYM(W0l, g_W0l) SYM(W1h, g_W1h) SYM(W1l, g_W1l)
    SYM(Wfh, g_Wfh) SYM(Wfl, g_Wfl) SYM(bp0, g_bp0) SYM(bp1, g_bp1)
    SYM(XYh, g_XYh) SYM(XYl, g_XYl) SYM(FXh, g_FXh) SYM(FXl, g_FXl)
    SYM(c0, g_c0) SYM(c1, g_c1) SYM(t1, g_t1) SYM(est, g_est)
    #undef SYM
    cudaGetSymbolAddress(&pv, g_H0h); __half (*H0h)[Bn*Hn] = (__half(*)[Bn*Hn])pv;
    cudaGetSymbolAddress(&pv, g_H0l); __half (*H0l)[Bn*Hn] = (__half(*)[Bn*Hn])pv;
    cudaGetSymbolAddress(&pv, g_H1h); __half (*H1h)[Bn*Hn] = (__half(*)[Bn*Hn])pv;
    cudaGetSymbolAddress(&pv, g_H1l); __half (*H1l)[Bn*Hn] = (__half(*)[Bn*Hn])pv;

    dim3 blk(256);
    dim3 gridZ(G4H / BN, Bn / BM);   // (32, 4)
    dim3 gridF(Hn / BN, Bn / BM);    // (8, 4)
    int cellBlocks = (Bn * Hn) / 256;
    int fc2Blocks  = (Bn * YDn * 32) / 256;
    int splitBlocks = 2048;

    // one-time: pack + split weights (gate-interleaved) and inputs
    split_kernel<<<splitBlocks, blk>>>(w_ih0, W0h, W0l, INn, 1280, 0,   G4H * INn, 1);
    split_kernel<<<splitBlocks, blk>>>(w_hh0, W0h, W0l, Hn,  1280, INn, G4H * Hn, 1);
    split_kernel<<<splitBlocks, blk>>>(w_ih1, W1h, W1l, Hn,  2048, 0,   G4H * Hn, 1);
    split_kernel<<<splitBlocks, blk>>>(w_hh1, W1h, W1l, Hn,  2048, Hn,  G4H * Hn, 1);
    split_kernel<<<splitBlocks, blk>>>(fc_w1, Wfh, Wfl, Hn,  1024, 0,   Hn * Hn, 0);
    split_kernel<<<splitBlocks, blk>>>(pre_x, XYh, XYl, XDn, INn, 0,    PREn * Bn * XDn, 0);
    split_kernel<<<splitBlocks, blk>>>(pre_y, XYh, XYl, YDn, INn, XDn,  PREn * Bn * YDn, 0);
    split_kernel<<<splitBlocks, blk>>>(fwd_x, FXh, FXl, XDn, INn, 0,    FWDn * Bn * XDn, 0);
    biaspack_kernel<<<16, blk>>>(b_ih0, b_hh0, bp0);
    biaspack_kernel<<<16, blk>>>(b_ih1, b_hh1, bp1);
    init_kernel<<<cellBlocks, blk>>>(pre_y);

    int T = 0;  // global step counter for ping-pong
    // ---------------- encode ----------------
    for (int t = 0; t < PREn; t++, T++) {
        int rd = T & 1, wr = 1 - rd;
        const __half* xyh = XYh + (size_t)t * Bn * INn;
        const __half* xyl = XYl + (size_t)t * Bn * INn;
        gemm_fp16x3<<<gridZ, blk, SMEMB>>>(
            xyh, xyl, INn, INn, H0h[rd], H0l[rd], Hn,
            W0h, W0l, 1280, 1280, G4H, bp0, 0, nullptr, c0, H0h[wr], H0l[wr]);
        gemm_fp16x3<<<gridZ, blk, SMEMB>>>(
            H0h[wr], H0l[wr], Hn, Hn, H1h[rd], H1l[rd], Hn,
            W1h, W1l, 2048, 2048, G4H, bp1, 0, nullptr, c1, H1h[wr], H1l[wr]);
    }

    // ---------------- decode ----------------
    for (int t = 0; t < FWDn; t++, T++) {
        int rd = T & 1, wr = 1 - rd;
        __half* fxh = FXh + (size_t)t * Bn * INn;
        __half* fxl = FXl + (size_t)t * Bn * INn;
        // fc1: t1 = tanh(h1 @ fc_w1^T + fc_b1)
        gemm_fp16x3<<<gridF, blk, SMEMB>>>(
            H1h[rd], H1l[rd], Hn, Hn, H1h[rd], H1l[rd], Hn,
            Wfh, Wfl, Hn, Hn, Hn, fc_b1, 1, t1, nullptr, nullptr, nullptr);
        // fc2 + residual; writes output[t] and est halves into FX[t]
        fc2_est_kernel<<<fc2Blocks, blk>>>(t1, fc_w2, fc_b2, est,
                                           outp + (size_t)t * Bn * YDn, fxh, fxl);
        gemm_fp16x3<<<gridZ, blk, SMEMB>>>(
            fxh, fxl, INn, INn, H0h[rd], H0l[rd], Hn,
            W0h, W0l, 1280, 1280, G4H, bp0, 0, nullptr, c0, H0h[wr], H0l[wr]);
        gemm_fp16x3<<<gridZ, blk, SMEMB>>>(
            H0h[wr], H0l[wr], Hn, Hn, H1h[rd], H1l[rd], Hn,
            W1h, W1l, 2048, 2048, G4H, bp1, 0, nullptr, c1, H1h[wr], H1l[wr]);
    }
}